// round 7
// baseline (speedup 1.0000x reference)
#include <cuda_runtime.h>
#include <cuda_bf16.h>
#include <cstdint>

#define NQ 12288
#define SPLIT 3
#define KPB (NQ / SPLIT)   // 4096
#define KT 64
#define NT (KPB / KT)      // 64 tiles per CTA
#define QT 128
#define VROW 144           // padded SMEM row stride for V^T (bytes)
#define VSP 72             // vS padded stride (uint16)

// ---- scratch (no cudaMalloc allowed) ----
__device__ __align__(16) unsigned char g_Qhi[NQ * 16];            // 8 bf16 (scaled q, hi)
__device__ __align__(16) unsigned char g_Qlo[NQ * 16];            // 8 bf16 (residual)
__device__ __align__(16) unsigned char g_Kd[NQ * 16];             // 8 bf16 per key
__device__ __align__(16) unsigned char g_Vt[(NQ / 64) * 8192];    // [tile][c 0..63][key 0..63] bf16
__device__ __align__(16) float g_num[SPLIT * NQ * 64];
__device__ __align__(16) float g_den[SPLIT * NQ];

// ============ helpers ============
__device__ __forceinline__ float ex2f(float x) {
    float r; asm("ex2.approx.ftz.f32 %0, %1;" : "=f"(r) : "f"(x)); return r;
}
__device__ __forceinline__ uint32_t pack_bf2(float lo, float hi) {
    uint32_t r;
    asm("cvt.rn.bf16x2.f32 %0, %1, %2;" : "=r"(r) : "f"(hi), "f"(lo));
    return r;
}
__device__ __forceinline__ void cp16(uint32_t dst, const void* src) {
    asm volatile("cp.async.ca.shared.global [%0], [%1], 16;" :: "r"(dst), "l"(src) : "memory");
}
#define CP_COMMIT() asm volatile("cp.async.commit_group;" ::: "memory")
#define CP_WAIT0()  asm volatile("cp.async.wait_group 0;" ::: "memory")

__device__ __forceinline__ uint32_t smem_u32(const void* p) {
    uint32_t a;
    asm("{ .reg .u64 t; cvta.to.shared.u64 t, %1; cvt.u32.u64 %0, t; }" : "=r"(a) : "l"(p));
    return a;
}
__device__ __forceinline__ void mma_bf16(float d[4], uint32_t a0, uint32_t a1, uint32_t a2,
                                         uint32_t a3, uint32_t b0, uint32_t b1) {
    asm volatile("mma.sync.aligned.m16n8k16.row.col.f32.bf16.bf16.f32 "
                 "{%0,%1,%2,%3}, {%4,%5,%6,%7}, {%8,%9}, {%0,%1,%2,%3};"
                 : "+f"(d[0]), "+f"(d[1]), "+f"(d[2]), "+f"(d[3])
                 : "r"(a0), "r"(a1), "r"(a2), "r"(a3), "r"(b0), "r"(b1));
}

// ---------------------------------------------------------------------------
// Kernel A: 4 threads per row, split by OUTPUT columns (conflict-free LDS).
// CTA = 64 rows, 256 threads, grid = 192.
// ---------------------------------------------------------------------------
__global__ __launch_bounds__(256) void qkv_kernel(
    const float* __restrict__ xm, const float* __restrict__ xd,
    const float* __restrict__ W1, const float* __restrict__ W2,
    const float* __restrict__ Wq, const float* __restrict__ Wk,
    const float* __restrict__ Wv) {
    __shared__ __align__(16) float4 W1s[192 * 4];
    __shared__ __align__(16) float4 W2s[16 * 4];
    __shared__ float Wqs[16 * 8];
    __shared__ float Wks[16 * 8];
    __shared__ __align__(16) float4 Wvs[16 * 16];
    __shared__ uint16_t vS[64 * VSP];

    const int tid = threadIdx.x;
    const int tp = tid & 3;           // output-column worker 0..3
    const int rl = tid >> 2;          // local row 0..63
    const int r = blockIdx.x * 64 + rl;
    const int lane = tid & 31;
    const int qbase2 = lane & ~3;     // quad base lane

    for (int i = tid; i < 192 * 4; i += 256) W1s[i] = ((const float4*)W1)[i];
    for (int i = tid; i < 16 * 4; i += 256) W2s[i] = ((const float4*)W2)[i];
    if (tid < 128) { Wqs[tid] = Wq[tid]; Wks[tid] = Wk[tid]; }
    for (int i = tid; i < 16 * 16; i += 256) Wvs[i] = ((const float4*)Wv)[i];
    __syncthreads();

    // ---- h1: this thread owns columns 4tp..4tp+3 over ALL 192 dims ----
    float h1p[4] = {0.f, 0.f, 0.f, 0.f};
    {
        const float4* xm4 = (const float4*)(xm + (size_t)r * 64);
        const float4* xd4 = (const float4*)(xd + (size_t)r * 128);
#pragma unroll
        for (int f = 0; f < 16; f++) {
            float4 xv = xm4[f];
            int d0 = 4 * f;
            float4 w0 = W1s[(d0 + 0) * 4 + tp];
            float4 w1 = W1s[(d0 + 1) * 4 + tp];
            float4 w2 = W1s[(d0 + 2) * 4 + tp];
            float4 w3 = W1s[(d0 + 3) * 4 + tp];
            h1p[0] = fmaf(xv.x, w0.x, h1p[0]); h1p[1] = fmaf(xv.x, w0.y, h1p[1]);
            h1p[2] = fmaf(xv.x, w0.z, h1p[2]); h1p[3] = fmaf(xv.x, w0.w, h1p[3]);
            h1p[0] = fmaf(xv.y, w1.x, h1p[0]); h1p[1] = fmaf(xv.y, w1.y, h1p[1]);
            h1p[2] = fmaf(xv.y, w1.z, h1p[2]); h1p[3] = fmaf(xv.y, w1.w, h1p[3]);
            h1p[0] = fmaf(xv.z, w2.x, h1p[0]); h1p[1] = fmaf(xv.z, w2.y, h1p[1]);
            h1p[2] = fmaf(xv.z, w2.z, h1p[2]); h1p[3] = fmaf(xv.z, w2.w, h1p[3]);
            h1p[0] = fmaf(xv.w, w3.x, h1p[0]); h1p[1] = fmaf(xv.w, w3.y, h1p[1]);
            h1p[2] = fmaf(xv.w, w3.z, h1p[2]); h1p[3] = fmaf(xv.w, w3.w, h1p[3]);
        }
#pragma unroll
        for (int f = 0; f < 32; f++) {
            float4 xv = xd4[f];
            int d0 = 64 + 4 * f;
            float4 w0 = W1s[(d0 + 0) * 4 + tp];
            float4 w1 = W1s[(d0 + 1) * 4 + tp];
            float4 w2 = W1s[(d0 + 2) * 4 + tp];
            float4 w3 = W1s[(d0 + 3) * 4 + tp];
            h1p[0] = fmaf(xv.x, w0.x, h1p[0]); h1p[1] = fmaf(xv.x, w0.y, h1p[1]);
            h1p[2] = fmaf(xv.x, w0.z, h1p[2]); h1p[3] = fmaf(xv.x, w0.w, h1p[3]);
            h1p[0] = fmaf(xv.y, w1.x, h1p[0]); h1p[1] = fmaf(xv.y, w1.y, h1p[1]);
            h1p[2] = fmaf(xv.y, w1.z, h1p[2]); h1p[3] = fmaf(xv.y, w1.w, h1p[3]);
            h1p[0] = fmaf(xv.z, w2.x, h1p[0]); h1p[1] = fmaf(xv.z, w2.y, h1p[1]);
            h1p[2] = fmaf(xv.z, w2.z, h1p[2]); h1p[3] = fmaf(xv.z, w2.w, h1p[3]);
            h1p[0] = fmaf(xv.w, w3.x, h1p[0]); h1p[1] = fmaf(xv.w, w3.y, h1p[1]);
            h1p[2] = fmaf(xv.w, w3.z, h1p[2]); h1p[3] = fmaf(xv.w, w3.w, h1p[3]);
        }
    }
#pragma unroll
    for (int c = 0; c < 4; c++) h1p[c] = fmaxf(h1p[c], 0.f);

    // gather h1 across quad
    float h1[16];
#pragma unroll
    for (int j = 0; j < 16; j++)
        h1[j] = __shfl_sync(0xffffffffu, h1p[j & 3], qbase2 | (j >> 2));

    // ---- h2: columns 4tp..4tp+3 ----
    float h2p[4] = {0.f, 0.f, 0.f, 0.f};
#pragma unroll
    for (int k = 0; k < 16; k++) {
        float4 w = W2s[k * 4 + tp];
        float hk = h1[k];
        h2p[0] = fmaf(hk, w.x, h2p[0]);
        h2p[1] = fmaf(hk, w.y, h2p[1]);
        h2p[2] = fmaf(hk, w.z, h2p[2]);
        h2p[3] = fmaf(hk, w.w, h2p[3]);
    }
#pragma unroll
    for (int c = 0; c < 4; c++) h2p[c] = fmaxf(h2p[c], 0.f);

    float h2[16];
#pragma unroll
    for (int j = 0; j < 16; j++)
        h2[j] = __shfl_sync(0xffffffffu, h2p[j & 3], qbase2 | (j >> 2));

    // ---- Q/K: outputs j = 2tp, 2tp+1 ----
    {
        float q0 = 0.f, q1 = 0.f, k0 = 0.f, k1 = 0.f;
        const int j0 = 2 * tp;
#pragma unroll
        for (int k = 0; k < 16; k++) {
            float hk = h2[k];
            q0 = fmaf(hk, Wqs[k * 8 + j0], q0);
            q1 = fmaf(hk, Wqs[k * 8 + j0 + 1], q1);
            k0 = fmaf(hk, Wks[k * 8 + j0], k0);
            k1 = fmaf(hk, Wks[k * 8 + j0 + 1], k1);
        }
        const float QS = (float)(1.4426950408889634 / 2.8284271247461903);
        q0 *= QS; q1 *= QS;
        __nv_bfloat16 h0 = __float2bfloat16(q0);
        __nv_bfloat16 h1b = __float2bfloat16(q1);
        float r0 = q0 - __bfloat162float(h0);
        float r1 = q1 - __bfloat162float(h1b);
        __nv_bfloat16 l0 = __float2bfloat16(r0);
        __nv_bfloat16 l1 = __float2bfloat16(r1);
        __nv_bfloat16 kb0 = __float2bfloat16(k0);
        __nv_bfloat16 kb1 = __float2bfloat16(k1);
        uint32_t hi = (uint32_t)*(uint16_t*)&h0 | ((uint32_t)*(uint16_t*)&h1b << 16);
        uint32_t lo = (uint32_t)*(uint16_t*)&l0 | ((uint32_t)*(uint16_t*)&l1 << 16);
        uint32_t kk = (uint32_t)*(uint16_t*)&kb0 | ((uint32_t)*(uint16_t*)&kb1 << 16);
        *(uint32_t*)(g_Qhi + (size_t)r * 16 + 4 * tp) = hi;
        *(uint32_t*)(g_Qlo + (size_t)r * 16 + 4 * tp) = lo;
        *(uint32_t*)(g_Kd + (size_t)r * 16 + 4 * tp) = kk;
    }

    // ---- V: cols [16tp, 16tp+16), rotated reads (conflict-free) ----
    {
        float v[16];
#pragma unroll
        for (int c = 0; c < 16; c++) v[c] = 0.f;
#pragma unroll
        for (int k = 0; k < 16; k++) {
            float hk = h2[k];
#pragma unroll
            for (int s = 0; s < 4; s++) {
                int c4 = (s + tp) & 3;
                float4 w = Wvs[k * 16 + tp * 4 + c4];
                v[4 * c4 + 0] = fmaf(hk, w.x, v[4 * c4 + 0]);
                v[4 * c4 + 1] = fmaf(hk, w.y, v[4 * c4 + 1]);
                v[4 * c4 + 2] = fmaf(hk, w.z, v[4 * c4 + 2]);
                v[4 * c4 + 3] = fmaf(hk, w.w, v[4 * c4 + 3]);
            }
        }
        // store to vS with XOR column swizzle (physical col pair = logical ^ X)
        const uint32_t X = ((uint32_t)rl >> 4) << 2;
        uint32_t* base = (uint32_t*)&vS[rl * VSP];
#pragma unroll
        for (int p = 0; p < 8; p++) {
            __nv_bfloat16 b0 = __float2bfloat16(v[2 * p]);
            __nv_bfloat16 b1 = __float2bfloat16(v[2 * p + 1]);
            uint32_t word = (uint32_t)*(uint16_t*)&b0 | ((uint32_t)*(uint16_t*)&b1 << 16);
            base[(16 * tp + ((2 * p) ^ X)) >> 1] = word;
        }
    }
    __syncthreads();

    // ---- transpose write: thread (c = tid>>2, part = tid&3), swizzled read ----
    {
        int c = tid >> 2, part = tid & 3;
        int cs = c ^ (part << 2);
        uint16_t tmp[16];
#pragma unroll
        for (int u = 0; u < 16; u++)
            tmp[u] = vS[(part * 16 + u) * VSP + cs];
        unsigned char* dst = g_Vt + (size_t)blockIdx.x * 8192 + (size_t)c * 128 + part * 32;
        *(uint4*)dst = *(uint4*)tmp;
        *(uint4*)(dst + 16) = *(uint4*)(tmp + 8);
    }
}

// ---------------------------------------------------------------------------
// Kernel B: mma.sync bf16 flash attention. CTA = 128 queries, 8 warps.
// ---------------------------------------------------------------------------
__device__ __forceinline__ void prefetch_tile(uint32_t sKb, uint32_t sVb, int tid,
                                              const unsigned char* kptr,
                                              const unsigned char* vptr) {
    if (tid < 64) cp16(sKb + tid * 16, kptr + tid * 16);
    int r0 = tid >> 3, s0 = tid & 7;
    cp16(sVb + r0 * VROW + s0 * 16, vptr + r0 * 128 + s0 * 16);
    int i1 = tid + 256;
    int r1 = i1 >> 3, s1 = i1 & 7;
    cp16(sVb + r1 * VROW + s1 * 16, vptr + r1 * 128 + s1 * 16);
    CP_COMMIT();
}

__global__ __launch_bounds__(256, 2) void attn_kernel() {
    __shared__ __align__(16) unsigned char sK[2][1024];
    __shared__ __align__(16) unsigned char sV[2][64 * VROW];

    const int tid = threadIdx.x;
    const int wid = tid >> 5, lane = tid & 31;
    const int gr = lane >> 2, tig = lane & 3;
    const int qbase = blockIdx.x * QT;
    const int kbase = blockIdx.y * KPB;
    const int tile0 = kbase >> 6;
    const int m0 = qbase + wid * 16 + gr;

    const uint32_t qa0 = *(const uint32_t*)(g_Qhi + (size_t)m0 * 16 + 4 * tig);
    const uint32_t qa1 = *(const uint32_t*)(g_Qhi + (size_t)(m0 + 8) * 16 + 4 * tig);
    const uint32_t qa2 = *(const uint32_t*)(g_Qlo + (size_t)m0 * 16 + 4 * tig);
    const uint32_t qa3 = *(const uint32_t*)(g_Qlo + (size_t)(m0 + 8) * 16 + 4 * tig);

    float o[8][4];
#pragma unroll
    for (int i = 0; i < 8; i++)
#pragma unroll
        for (int j = 0; j < 4; j++) o[i][j] = 0.f;
    float den0 = 0.f, den1 = 0.f;

    const uint32_t sKb0 = smem_u32(sK[0]), sKb1 = smem_u32(sK[1]);
    const uint32_t sVb0 = smem_u32(sV[0]), sVb1 = smem_u32(sV[1]);

    prefetch_tile(sKb0, sVb0, tid, g_Kd + (size_t)kbase * 16, g_Vt + (size_t)tile0 * 8192);

    for (int t = 0; t < NT; t++) {
        CP_WAIT0();
        __syncthreads();
        if (t + 1 < NT) {
            int st = (t + 1) & 1;
            prefetch_tile(st ? sKb1 : sKb0, st ? sVb1 : sVb0, tid,
                          g_Kd + (size_t)(kbase + (t + 1) * 64) * 16,
                          g_Vt + (size_t)(tile0 + t + 1) * 8192);
        }
        const unsigned char* Ks = sK[t & 1];
        const unsigned char* Vs = sV[t & 1];

#pragma unroll
        for (int kc = 0; kc < 4; kc++) {
            float s0[4] = {0.f, 0.f, 0.f, 0.f};
            float s1[4] = {0.f, 0.f, 0.f, 0.f};
            uint32_t kb0 = *(const uint32_t*)(Ks + (16 * kc + gr) * 16 + 4 * tig);
            uint32_t kb1 = *(const uint32_t*)(Ks + (16 * kc + 8 + gr) * 16 + 4 * tig);
            mma_bf16(s0, qa0, qa1, qa2, qa3, kb0, kb0);
            mma_bf16(s1, qa0, qa1, qa2, qa3, kb1, kb1);

            float e00 = ex2f(s0[0]), e01 = ex2f(s0[1]), e02 = ex2f(s0[2]), e03 = ex2f(s0[3]);
            float e10 = ex2f(s1[0]), e11 = ex2f(s1[1]), e12 = ex2f(s1[2]), e13 = ex2f(s1[3]);
            den0 += (e00 + e01) + (e10 + e11);
            den1 += (e02 + e03) + (e12 + e13);
            uint32_t pa0 = pack_bf2(e00, e01);
            uint32_t pa1 = pack_bf2(e02, e03);
            uint32_t pa2 = pack_bf2(e10, e11);
            uint32_t pa3 = pack_bf2(e12, e13);

            const unsigned char* vb = Vs + gr * VROW + 32 * kc + 4 * tig;
#pragma unroll
            for (int nb = 0; nb < 8; nb++) {
                uint32_t vb0 = *(const uint32_t*)(vb + nb * 8 * VROW);
                uint32_t vb1 = *(const uint32_t*)(vb + nb * 8 * VROW + 16);
                mma_bf16(o[nb], pa0, pa1, pa2, pa3, vb0, vb1);
            }
        }
        __syncthreads();
    }

    den0 += __shfl_xor_sync(0xffffffffu, den0, 1);
    den0 += __shfl_xor_sync(0xffffffffu, den0, 2);
    den1 += __shfl_xor_sync(0xffffffffu, den1, 1);
    den1 += __shfl_xor_sync(0xffffffffu, den1, 2);
    if (tig == 0) {
        g_den[blockIdx.y * NQ + m0] = den0;
        g_den[blockIdx.y * NQ + m0 + 8] = den1;
    }

    float* np0 = g_num + ((size_t)blockIdx.y * NQ + m0) * 64;
    float* np1 = np0 + 8 * 64;
#pragma unroll
    for (int nb = 0; nb < 8; nb++) {
        *(float2*)(np0 + 8 * nb + 2 * tig) = make_float2(o[nb][0], o[nb][1]);
        *(float2*)(np1 + 8 * nb + 2 * tig) = make_float2(o[nb][2], o[nb][3]);
    }
}

// ---------------------------------------------------------------------------
// Kernel C: combine splits + divide
// ---------------------------------------------------------------------------
__global__ void combine_kernel(float* __restrict__ out) {
    int i = blockIdx.x * blockDim.x + threadIdx.x;
    if (i >= NQ * 64) return;
    int r = i >> 6;
    float s = 0.f, d = 0.f;
#pragma unroll
    for (int p = 0; p < SPLIT; p++) {
        s += g_num[(size_t)p * NQ * 64 + i];
        d += g_den[p * NQ + r];
    }
    out[i] = s / d;
}

extern "C" void kernel_launch(void* const* d_in, const int* in_sizes, int n_in,
                              void* d_out, int out_size) {
    const float* xm = (const float*)d_in[0];
    const float* xd = (const float*)d_in[1];
    const float* W1 = (const float*)d_in[3];
    const float* W2 = (const float*)d_in[4];
    const float* Wq = (const float*)d_in[5];
    const float* Wk = (const float*)d_in[6];
    const float* Wv = (const float*)d_in[7];

    qkv_kernel<<<NQ / 64, 256>>>(xm, xd, W1, W2, Wq, Wk, Wv);
    attn_kernel<<<dim3(NQ / QT, SPLIT), 256>>>();
    combine_kernel<<<(NQ * 64 + 255) / 256, 256>>>((float*)d_out);
}

// round 8
// speedup vs baseline: 1.5194x; 1.5194x over previous
#include <cuda_runtime.h>
#include <cuda_bf16.h>
#include <cstdint>

#define NQ 12288
#define SPLIT 3
#define KPB (NQ / SPLIT)   // 4096
#define KT 64
#define NT (KPB / KT)      // 64 tiles per CTA
#define QT 128
#define VROW 144           // padded SMEM row stride for V^T (bytes)

// ---- scratch (no cudaMalloc allowed) ----
__device__ __align__(16) unsigned char g_Qhi[NQ * 16];            // 8 bf16 (scaled q, hi)
__device__ __align__(16) unsigned char g_Qlo[NQ * 16];            // 8 bf16 (residual)
__device__ __align__(16) unsigned char g_Kd[NQ * 16];             // 8 bf16 per key
__device__ __align__(16) unsigned char g_Vt[(NQ / 64) * 8192];    // [tile][c 0..63][key 0..63] bf16
__device__ __align__(16) float g_num[SPLIT * NQ * 64];
__device__ __align__(16) float g_den[SPLIT * NQ];

// ============ helpers ============
__device__ __forceinline__ float ex2f(float x) {
    float r; asm("ex2.approx.ftz.f32 %0, %1;" : "=f"(r) : "f"(x)); return r;
}
// pack (lo, hi) floats -> bf16x2 (lo in low half)
__device__ __forceinline__ uint32_t pack_bf2(float lo, float hi) {
    uint32_t r;
    asm("cvt.rn.bf16x2.f32 %0, %1, %2;" : "=r"(r) : "f"(hi), "f"(lo));
    return r;
}
__device__ __forceinline__ void cp16(uint32_t dst, const void* src) {
    asm volatile("cp.async.ca.shared.global [%0], [%1], 16;" :: "r"(dst), "l"(src) : "memory");
}
#define CP_COMMIT() asm volatile("cp.async.commit_group;" ::: "memory")
#define CP_WAIT0()  asm volatile("cp.async.wait_group 0;" ::: "memory")

__device__ __forceinline__ uint32_t smem_u32(const void* p) {
    uint32_t a;
    asm("{ .reg .u64 t; cvta.to.shared.u64 t, %1; cvt.u32.u64 %0, t; }" : "=r"(a) : "l"(p));
    return a;
}
__device__ __forceinline__ void mma_bf16(float d[4], uint32_t a0, uint32_t a1, uint32_t a2,
                                         uint32_t a3, uint32_t b0, uint32_t b1) {
    asm volatile("mma.sync.aligned.m16n8k16.row.col.f32.bf16.bf16.f32 "
                 "{%0,%1,%2,%3}, {%4,%5,%6,%7}, {%8,%9}, {%0,%1,%2,%3};"
                 : "+f"(d[0]), "+f"(d[1]), "+f"(d[2]), "+f"(d[3])
                 : "r"(a0), "r"(a1), "r"(a2), "r"(a3), "r"(b0), "r"(b1));
}

// ---------------------------------------------------------------------------
// Kernel A: mma.sync QKV. CTA = 128 rows, 8 warps (one m16 block each).
// A-side: single bf16 (row-random rounding averages out under softmax).
// B-side: hi/lo bf16 frags precomputed in SMEM (weight error is coherent).
// ---------------------------------------------------------------------------
__global__ __launch_bounds__(256) void qkv_kernel(
    const float* __restrict__ xm, const float* __restrict__ xd,
    const float* __restrict__ W1, const float* __restrict__ W2,
    const float* __restrict__ Wq, const float* __restrict__ Wk,
    const float* __restrict__ Wv) {
    __shared__ uint32_t fHi[72][32];
    __shared__ uint32_t fLo[72][32];
    __shared__ uint16_t vS[128 * 66];

    const int tid = threadIdx.x;
    const int wid = tid >> 5, lane = tid & 31;
    const int gr = lane >> 2, tig = lane & 3;
    const float QS = (float)(1.4426950408889634 / 2.8284271247461903);  // log2(e)/sqrt(8)

    // ---- precompute B fragments (hi/lo) for all weights ----
    // units: 0..47 W1 (12 ksteps x 2 nb x 2 reg), 48..51 W2, 52..55 [Wq*QS|Wk], 56..71 Wv
    for (int u = wid; u < 72; u += 8) {
        int k, col, stride; const float* src; float scale = 1.f;
        if (u < 48) {
            int ks = u >> 2, nb = (u >> 1) & 1, reg = u & 1;
            k = 16 * ks + 2 * tig + 8 * reg; col = gr + 8 * nb; src = W1; stride = 16;
        } else if (u < 52) {
            int v = u - 48, nb = (v >> 1) & 1, reg = v & 1;
            k = 2 * tig + 8 * reg; col = gr + 8 * nb; src = W2; stride = 16;
        } else if (u < 56) {
            int v = u - 52, nb = (v >> 1) & 1, reg = v & 1;
            k = 2 * tig + 8 * reg; col = gr; src = nb ? Wk : Wq; stride = 8;
            if (!nb) scale = QS;
        } else {
            int v = u - 56, nb = v >> 1, reg = v & 1;
            k = 2 * tig + 8 * reg; col = 8 * nb + gr; src = Wv; stride = 64;
        }
        float w0 = src[k * stride + col] * scale;
        float w1 = src[(k + 1) * stride + col] * scale;
        uint32_t hi = pack_bf2(w0, w1);
        float f0 = __uint_as_float(hi << 16);
        float f1 = __uint_as_float(hi & 0xffff0000u);
        uint32_t lo = pack_bf2(w0 - f0, w1 - f1);
        fHi[u][lane] = hi;
        fLo[u][lane] = lo;
    }
    __syncthreads();

    const int lr0 = wid * 16 + gr;                 // local row of c0/c1 (c2/c3: +8)
    const int r0 = blockIdx.x * 128 + lr0;

    // ---- h1 = relu(X @ W1), K=192 in 12 ksteps ----
    float c0[4] = {0.f, 0.f, 0.f, 0.f}, c1[4] = {0.f, 0.f, 0.f, 0.f};
    {
        const float* pr0m = xm + (size_t)r0 * 64;
        const float* pr1m = pr0m + 8 * 64;
        const float* pr0d = xd + (size_t)r0 * 128;
        const float* pr1d = pr0d + 8 * 128;
#pragma unroll
        for (int ks = 0; ks < 12; ks++) {
            const float* p0 = (ks < 4) ? (pr0m + 16 * ks) : (pr0d + 16 * ks - 64);
            const float* p1 = (ks < 4) ? (pr1m + 16 * ks) : (pr1d + 16 * ks - 64);
            float2 x00 = *(const float2*)(p0 + 2 * tig);
            float2 x01 = *(const float2*)(p0 + 2 * tig + 8);
            float2 x10 = *(const float2*)(p1 + 2 * tig);
            float2 x11 = *(const float2*)(p1 + 2 * tig + 8);
            uint32_t a0 = pack_bf2(x00.x, x00.y);
            uint32_t a1 = pack_bf2(x10.x, x10.y);
            uint32_t a2 = pack_bf2(x01.x, x01.y);
            uint32_t a3 = pack_bf2(x11.x, x11.y);
            int u = 4 * ks;
            mma_bf16(c0, a0, a1, a2, a3, fHi[u][lane], fHi[u + 1][lane]);
            mma_bf16(c0, a0, a1, a2, a3, fLo[u][lane], fLo[u + 1][lane]);
            mma_bf16(c1, a0, a1, a2, a3, fHi[u + 2][lane], fHi[u + 3][lane]);
            mma_bf16(c1, a0, a1, a2, a3, fLo[u + 2][lane], fLo[u + 3][lane]);
        }
    }
    // relu + repack C-frags -> A-frags (c-layout == a-layout for N=16)
    uint32_t a0 = pack_bf2(fmaxf(c0[0], 0.f), fmaxf(c0[1], 0.f));
    uint32_t a1 = pack_bf2(fmaxf(c0[2], 0.f), fmaxf(c0[3], 0.f));
    uint32_t a2 = pack_bf2(fmaxf(c1[0], 0.f), fmaxf(c1[1], 0.f));
    uint32_t a3 = pack_bf2(fmaxf(c1[2], 0.f), fmaxf(c1[3], 0.f));

    // ---- h2 = relu(h1 @ W2) ----
    float d0[4] = {0.f, 0.f, 0.f, 0.f}, d1[4] = {0.f, 0.f, 0.f, 0.f};
    mma_bf16(d0, a0, a1, a2, a3, fHi[48][lane], fHi[49][lane]);
    mma_bf16(d0, a0, a1, a2, a3, fLo[48][lane], fLo[49][lane]);
    mma_bf16(d1, a0, a1, a2, a3, fHi[50][lane], fHi[51][lane]);
    mma_bf16(d1, a0, a1, a2, a3, fLo[50][lane], fLo[51][lane]);

    uint32_t h0 = pack_bf2(fmaxf(d0[0], 0.f), fmaxf(d0[1], 0.f));
    uint32_t h1 = pack_bf2(fmaxf(d0[2], 0.f), fmaxf(d0[3], 0.f));
    uint32_t h2r = pack_bf2(fmaxf(d1[0], 0.f), fmaxf(d1[1], 0.f));
    uint32_t h3 = pack_bf2(fmaxf(d1[2], 0.f), fmaxf(d1[3], 0.f));

    // ---- Q (pre-scaled) and K ----
    float qc[4] = {0.f, 0.f, 0.f, 0.f}, kc[4] = {0.f, 0.f, 0.f, 0.f};
    mma_bf16(qc, h0, h1, h2r, h3, fHi[52][lane], fHi[53][lane]);
    mma_bf16(qc, h0, h1, h2r, h3, fLo[52][lane], fLo[53][lane]);
    mma_bf16(kc, h0, h1, h2r, h3, fHi[54][lane], fHi[55][lane]);
    mma_bf16(kc, h0, h1, h2r, h3, fLo[54][lane], fLo[55][lane]);

    {
        uint32_t qhiA = pack_bf2(qc[0], qc[1]);
        uint32_t qhiB = pack_bf2(qc[2], qc[3]);
        float fA0 = __uint_as_float(qhiA << 16);
        float fA1 = __uint_as_float(qhiA & 0xffff0000u);
        float fB0 = __uint_as_float(qhiB << 16);
        float fB1 = __uint_as_float(qhiB & 0xffff0000u);
        uint32_t qloA = pack_bf2(qc[0] - fA0, qc[1] - fA1);
        uint32_t qloB = pack_bf2(qc[2] - fB0, qc[3] - fB1);
        uint32_t kA = pack_bf2(kc[0], kc[1]);
        uint32_t kB = pack_bf2(kc[2], kc[3]);
        *(uint32_t*)(g_Qhi + (size_t)r0 * 16 + 4 * tig) = qhiA;
        *(uint32_t*)(g_Qhi + (size_t)(r0 + 8) * 16 + 4 * tig) = qhiB;
        *(uint32_t*)(g_Qlo + (size_t)r0 * 16 + 4 * tig) = qloA;
        *(uint32_t*)(g_Qlo + (size_t)(r0 + 8) * 16 + 4 * tig) = qloB;
        *(uint32_t*)(g_Kd + (size_t)r0 * 16 + 4 * tig) = kA;
        *(uint32_t*)(g_Kd + (size_t)(r0 + 8) * 16 + 4 * tig) = kB;
    }

    // ---- V = h2 @ Wv (N=64, 8 nblocks), stage bf16 in vS ----
#pragma unroll
    for (int nb = 0; nb < 8; nb++) {
        float vc[4] = {0.f, 0.f, 0.f, 0.f};
        int u = 56 + 2 * nb;
        mma_bf16(vc, h0, h1, h2r, h3, fHi[u][lane], fHi[u + 1][lane]);
        mma_bf16(vc, h0, h1, h2r, h3, fLo[u][lane], fLo[u + 1][lane]);
        int colw = 8 * nb + 2 * tig;
        *(uint32_t*)&vS[lr0 * 66 + colw] = pack_bf2(vc[0], vc[1]);
        *(uint32_t*)&vS[(lr0 + 8) * 66 + colw] = pack_bf2(vc[2], vc[3]);
    }
    __syncthreads();

    // ---- transposed coalesced write (proven R5 block): 128 threads ----
    if (tid < 128) {
        int tt = tid >> 6, c = tid & 63;
        unsigned char* dst = g_Vt + (size_t)(blockIdx.x * 2 + tt) * 8192 + (size_t)c * 128;
#pragma unroll
        for (int seg = 0; seg < 8; seg++) {
            uint16_t tmp[8];
#pragma unroll
            for (int u = 0; u < 8; u++)
                tmp[u] = vS[(tt * 64 + seg * 8 + u) * 66 + c];
            *(uint4*)(dst + seg * 16) = *(uint4*)tmp;
        }
    }
}

// ---------------------------------------------------------------------------
// Kernel B: mma.sync bf16 flash attention. CTA = 128 queries, 8 warps.
// ---------------------------------------------------------------------------
__device__ __forceinline__ void prefetch_tile(uint32_t sKb, uint32_t sVb, int tid,
                                              const unsigned char* kptr,
                                              const unsigned char* vptr) {
    if (tid < 64) cp16(sKb + tid * 16, kptr + tid * 16);
    int r0 = tid >> 3, s0 = tid & 7;
    cp16(sVb + r0 * VROW + s0 * 16, vptr + r0 * 128 + s0 * 16);
    int i1 = tid + 256;
    int r1 = i1 >> 3, s1 = i1 & 7;
    cp16(sVb + r1 * VROW + s1 * 16, vptr + r1 * 128 + s1 * 16);
    CP_COMMIT();
}

__global__ __launch_bounds__(256, 2) void attn_kernel() {
    __shared__ __align__(16) unsigned char sK[2][1024];
    __shared__ __align__(16) unsigned char sV[2][64 * VROW];

    const int tid = threadIdx.x;
    const int wid = tid >> 5, lane = tid & 31;
    const int gr = lane >> 2, tig = lane & 3;
    const int qbase = blockIdx.x * QT;
    const int kbase = blockIdx.y * KPB;
    const int tile0 = kbase >> 6;
    const int m0 = qbase + wid * 16 + gr;

    const uint32_t qa0 = *(const uint32_t*)(g_Qhi + (size_t)m0 * 16 + 4 * tig);
    const uint32_t qa1 = *(const uint32_t*)(g_Qhi + (size_t)(m0 + 8) * 16 + 4 * tig);
    const uint32_t qa2 = *(const uint32_t*)(g_Qlo + (size_t)m0 * 16 + 4 * tig);
    const uint32_t qa3 = *(const uint32_t*)(g_Qlo + (size_t)(m0 + 8) * 16 + 4 * tig);

    float o[8][4];
#pragma unroll
    for (int i = 0; i < 8; i++)
#pragma unroll
        for (int j = 0; j < 4; j++) o[i][j] = 0.f;
    float den0 = 0.f, den1 = 0.f;

    const uint32_t sKb0 = smem_u32(sK[0]), sKb1 = smem_u32(sK[1]);
    const uint32_t sVb0 = smem_u32(sV[0]), sVb1 = smem_u32(sV[1]);

    prefetch_tile(sKb0, sVb0, tid, g_Kd + (size_t)kbase * 16, g_Vt + (size_t)tile0 * 8192);

    for (int t = 0; t < NT; t++) {
        CP_WAIT0();
        __syncthreads();
        if (t + 1 < NT) {
            int st = (t + 1) & 1;
            prefetch_tile(st ? sKb1 : sKb0, st ? sVb1 : sVb0, tid,
                          g_Kd + (size_t)(kbase + (t + 1) * 64) * 16,
                          g_Vt + (size_t)(tile0 + t + 1) * 8192);
        }
        const unsigned char* Ks = sK[t & 1];
        const unsigned char* Vs = sV[t & 1];

#pragma unroll
        for (int kc = 0; kc < 4; kc++) {
            float s0[4] = {0.f, 0.f, 0.f, 0.f};
            float s1[4] = {0.f, 0.f, 0.f, 0.f};
            uint32_t kb0 = *(const uint32_t*)(Ks + (16 * kc + gr) * 16 + 4 * tig);
            uint32_t kb1 = *(const uint32_t*)(Ks + (16 * kc + 8 + gr) * 16 + 4 * tig);
            mma_bf16(s0, qa0, qa1, qa2, qa3, kb0, kb0);
            mma_bf16(s1, qa0, qa1, qa2, qa3, kb1, kb1);

            float e00 = ex2f(s0[0]), e01 = ex2f(s0[1]), e02 = ex2f(s0[2]), e03 = ex2f(s0[3]);
            float e10 = ex2f(s1[0]), e11 = ex2f(s1[1]), e12 = ex2f(s1[2]), e13 = ex2f(s1[3]);
            den0 += (e00 + e01) + (e10 + e11);
            den1 += (e02 + e03) + (e12 + e13);
            uint32_t pa0 = pack_bf2(e00, e01);
            uint32_t pa1 = pack_bf2(e02, e03);
            uint32_t pa2 = pack_bf2(e10, e11);
            uint32_t pa3 = pack_bf2(e12, e13);

            const unsigned char* vb = Vs + gr * VROW + 32 * kc + 4 * tig;
#pragma unroll
            for (int nb = 0; nb < 8; nb++) {
                uint32_t vb0 = *(const uint32_t*)(vb + nb * 8 * VROW);
                uint32_t vb1 = *(const uint32_t*)(vb + nb * 8 * VROW + 16);
                mma_bf16(o[nb], pa0, pa1, pa2, pa3, vb0, vb1);
            }
        }
        __syncthreads();
    }

    den0 += __shfl_xor_sync(0xffffffffu, den0, 1);
    den0 += __shfl_xor_sync(0xffffffffu, den0, 2);
    den1 += __shfl_xor_sync(0xffffffffu, den1, 1);
    den1 += __shfl_xor_sync(0xffffffffu, den1, 2);
    if (tig == 0) {
        g_den[blockIdx.y * NQ + m0] = den0;
        g_den[blockIdx.y * NQ + m0 + 8] = den1;
    }

    float* np0 = g_num + ((size_t)blockIdx.y * NQ + m0) * 64;
    float* np1 = np0 + 8 * 64;
#pragma unroll
    for (int nb = 0; nb < 8; nb++) {
        *(float2*)(np0 + 8 * nb + 2 * tig) = make_float2(o[nb][0], o[nb][1]);
        *(float2*)(np1 + 8 * nb + 2 * tig) = make_float2(o[nb][2], o[nb][3]);
    }
}

// ---------------------------------------------------------------------------
// Kernel C: combine splits + divide
// ---------------------------------------------------------------------------
__global__ void combine_kernel(float* __restrict__ out) {
    int i = blockIdx.x * blockDim.x + threadIdx.x;
    if (i >= NQ * 64) return;
    int r = i >> 6;
    float s = 0.f, d = 0.f;
#pragma unroll
    for (int p = 0; p < SPLIT; p++) {
        s += g_num[(size_t)p * NQ * 64 + i];
        d += g_den[p * NQ + r];
    }
    out[i] = s / d;
}

extern "C" void kernel_launch(void* const* d_in, const int* in_sizes, int n_in,
                              void* d_out, int out_size) {
    const float* xm = (const float*)d_in[0];
    const float* xd = (const float*)d_in[1];
    const float* W1 = (const float*)d_in[3];
    const float* W2 = (const float*)d_in[4];
    const float* Wq = (const float*)d_in[5];
    const float* Wk = (const float*)d_in[6];
    const float* Wv = (const float*)d_in[7];

    qkv_kernel<<<NQ / 128, 256>>>(xm, xd, W1, W2, Wq, Wk, Wv);
    attn_kernel<<<dim3(NQ / QT, SPLIT), 256>>>();
    combine_kernel<<<(NQ * 64 + 255) / 256, 256>>>((float*)d_out);
}

// round 9
// speedup vs baseline: 1.5956x; 1.0501x over previous
#include <cuda_runtime.h>
#include <cuda_bf16.h>
#include <cstdint>

#define NQ 12288
#define SPLIT 3
#define KPB (NQ / SPLIT)   // 4096
#define NT (KPB / 64)      // 64 tiles per CTA
#define QT 128
#define VROW 144           // padded SMEM row stride for V^T (bytes)

// ---- scratch (no cudaMalloc allowed) ----
__device__ __align__(16) unsigned char g_Qhi[NQ * 16];
__device__ __align__(16) unsigned char g_Qlo[NQ * 16];
__device__ __align__(16) unsigned char g_Kd[NQ * 16];
__device__ __align__(16) unsigned char g_Vt[(NQ / 64) * 8192];
__device__ __align__(16) float g_num[SPLIT * NQ * 64];
__device__ __align__(16) float g_den[SPLIT * NQ];

// ============ helpers ============
__device__ __forceinline__ float ex2f(float x) {
    float r; asm("ex2.approx.ftz.f32 %0, %1;" : "=f"(r) : "f"(x)); return r;
}
__device__ __forceinline__ uint32_t pack_bf2(float lo, float hi) {
    uint32_t r;
    asm("cvt.rn.bf16x2.f32 %0, %1, %2;" : "=r"(r) : "f"(hi), "f"(lo));
    return r;
}
__device__ __forceinline__ void cp16(uint32_t dst, const void* src) {
    asm volatile("cp.async.ca.shared.global [%0], [%1], 16;" :: "r"(dst), "l"(src) : "memory");
}
#define CP_COMMIT() asm volatile("cp.async.commit_group;" ::: "memory")
#define CP_WAIT0()  asm volatile("cp.async.wait_group 0;" ::: "memory")

__device__ __forceinline__ uint32_t smem_u32(const void* p) {
    uint32_t a;
    asm("{ .reg .u64 t; cvta.to.shared.u64 t, %1; cvt.u32.u64 %0, t; }" : "=r"(a) : "l"(p));
    return a;
}
__device__ __forceinline__ void mma_bf16(float d[4], uint32_t a0, uint32_t a1, uint32_t a2,
                                         uint32_t a3, uint32_t b0, uint32_t b1) {
    asm volatile("mma.sync.aligned.m16n8k16.row.col.f32.bf16.bf16.f32 "
                 "{%0,%1,%2,%3}, {%4,%5,%6,%7}, {%8,%9}, {%0,%1,%2,%3};"
                 : "+f"(d[0]), "+f"(d[1]), "+f"(d[2]), "+f"(d[3])
                 : "r"(a0), "r"(a1), "r"(a2), "r"(a3), "r"(b0), "r"(b1));
}
__device__ __forceinline__ void ldsm_x4(uint32_t& r0, uint32_t& r1, uint32_t& r2, uint32_t& r3,
                                        uint32_t addr) {
    asm volatile("ldmatrix.sync.aligned.m8n8.x4.shared.b16 {%0,%1,%2,%3}, [%4];"
                 : "=r"(r0), "=r"(r1), "=r"(r2), "=r"(r3) : "r"(addr));
}
__device__ __forceinline__ void ldsm_x2(uint32_t& r0, uint32_t& r1, uint32_t addr) {
    asm volatile("ldmatrix.sync.aligned.m8n8.x2.shared.b16 {%0,%1}, [%2];"
                 : "=r"(r0), "=r"(r1) : "r"(addr));
}

// ---------------------------------------------------------------------------
// Kernel A: mma.sync QKV. CTA = 64 rows, 4 warps. Grid = 192 (fills all SMs).
// ---------------------------------------------------------------------------
__global__ __launch_bounds__(128) void qkv_kernel(
    const float* __restrict__ xm, const float* __restrict__ xd,
    const float* __restrict__ W1, const float* __restrict__ W2,
    const float* __restrict__ Wq, const float* __restrict__ Wk,
    const float* __restrict__ Wv) {
    __shared__ uint32_t fHi[72][32];
    __shared__ uint32_t fLo[72][32];
    __shared__ uint16_t vS[64 * 66];

    const int tid = threadIdx.x;
    const int wid = tid >> 5, lane = tid & 31;
    const int gr = lane >> 2, tig = lane & 3;
    const float QS = (float)(1.4426950408889634 / 2.8284271247461903);

    // ---- precompute B fragments (hi/lo) for all weights ----
    for (int u = wid; u < 72; u += 4) {
        int k, col, stride; const float* src; float scale = 1.f;
        if (u < 48) {
            int ks = u >> 2, nb = (u >> 1) & 1, reg = u & 1;
            k = 16 * ks + 2 * tig + 8 * reg; col = gr + 8 * nb; src = W1; stride = 16;
        } else if (u < 52) {
            int v = u - 48, nb = (v >> 1) & 1, reg = v & 1;
            k = 2 * tig + 8 * reg; col = gr + 8 * nb; src = W2; stride = 16;
        } else if (u < 56) {
            int v = u - 52, nb = (v >> 1) & 1, reg = v & 1;
            k = 2 * tig + 8 * reg; col = gr; src = nb ? Wk : Wq; stride = 8;
            if (!nb) scale = QS;
        } else {
            int v = u - 56, nb = v >> 1, reg = v & 1;
            k = 2 * tig + 8 * reg; col = 8 * nb + gr; src = Wv; stride = 64;
        }
        float w0 = src[k * stride + col] * scale;
        float w1 = src[(k + 1) * stride + col] * scale;
        uint32_t hi = pack_bf2(w0, w1);
        float f0 = __uint_as_float(hi << 16);
        float f1 = __uint_as_float(hi & 0xffff0000u);
        uint32_t lo = pack_bf2(w0 - f0, w1 - f1);
        fHi[u][lane] = hi;
        fLo[u][lane] = lo;
    }
    __syncthreads();

    const int lr0 = wid * 16 + gr;
    const int r0 = blockIdx.x * 64 + lr0;

    // ---- h1 = relu(X @ W1) ----
    float c0[4] = {0.f, 0.f, 0.f, 0.f}, c1[4] = {0.f, 0.f, 0.f, 0.f};
    {
        const float* pr0m = xm + (size_t)r0 * 64;
        const float* pr1m = pr0m + 8 * 64;
        const float* pr0d = xd + (size_t)r0 * 128;
        const float* pr1d = pr0d + 8 * 128;
#pragma unroll
        for (int ks = 0; ks < 12; ks++) {
            const float* p0 = (ks < 4) ? (pr0m + 16 * ks) : (pr0d + 16 * ks - 64);
            const float* p1 = (ks < 4) ? (pr1m + 16 * ks) : (pr1d + 16 * ks - 64);
            float2 x00 = *(const float2*)(p0 + 2 * tig);
            float2 x01 = *(const float2*)(p0 + 2 * tig + 8);
            float2 x10 = *(const float2*)(p1 + 2 * tig);
            float2 x11 = *(const float2*)(p1 + 2 * tig + 8);
            uint32_t a0 = pack_bf2(x00.x, x00.y);
            uint32_t a1 = pack_bf2(x10.x, x10.y);
            uint32_t a2 = pack_bf2(x01.x, x01.y);
            uint32_t a3 = pack_bf2(x11.x, x11.y);
            int u = 4 * ks;
            mma_bf16(c0, a0, a1, a2, a3, fHi[u][lane], fHi[u + 1][lane]);
            mma_bf16(c0, a0, a1, a2, a3, fLo[u][lane], fLo[u + 1][lane]);
            mma_bf16(c1, a0, a1, a2, a3, fHi[u + 2][lane], fHi[u + 3][lane]);
            mma_bf16(c1, a0, a1, a2, a3, fLo[u + 2][lane], fLo[u + 3][lane]);
        }
    }
    uint32_t a0 = pack_bf2(fmaxf(c0[0], 0.f), fmaxf(c0[1], 0.f));
    uint32_t a1 = pack_bf2(fmaxf(c0[2], 0.f), fmaxf(c0[3], 0.f));
    uint32_t a2 = pack_bf2(fmaxf(c1[0], 0.f), fmaxf(c1[1], 0.f));
    uint32_t a3 = pack_bf2(fmaxf(c1[2], 0.f), fmaxf(c1[3], 0.f));

    // ---- h2 = relu(h1 @ W2) ----
    float d0[4] = {0.f, 0.f, 0.f, 0.f}, d1[4] = {0.f, 0.f, 0.f, 0.f};
    mma_bf16(d0, a0, a1, a2, a3, fHi[48][lane], fHi[49][lane]);
    mma_bf16(d0, a0, a1, a2, a3, fLo[48][lane], fLo[49][lane]);
    mma_bf16(d1, a0, a1, a2, a3, fHi[50][lane], fHi[51][lane]);
    mma_bf16(d1, a0, a1, a2, a3, fLo[50][lane], fLo[51][lane]);

    uint32_t h0 = pack_bf2(fmaxf(d0[0], 0.f), fmaxf(d0[1], 0.f));
    uint32_t h1 = pack_bf2(fmaxf(d0[2], 0.f), fmaxf(d0[3], 0.f));
    uint32_t h2r = pack_bf2(fmaxf(d1[0], 0.f), fmaxf(d1[1], 0.f));
    uint32_t h3 = pack_bf2(fmaxf(d1[2], 0.f), fmaxf(d1[3], 0.f));

    // ---- Q (pre-scaled) and K ----
    float qc[4] = {0.f, 0.f, 0.f, 0.f}, kc[4] = {0.f, 0.f, 0.f, 0.f};
    mma_bf16(qc, h0, h1, h2r, h3, fHi[52][lane], fHi[53][lane]);
    mma_bf16(qc, h0, h1, h2r, h3, fLo[52][lane], fLo[53][lane]);
    mma_bf16(kc, h0, h1, h2r, h3, fHi[54][lane], fHi[55][lane]);
    mma_bf16(kc, h0, h1, h2r, h3, fLo[54][lane], fLo[55][lane]);

    {
        uint32_t qhiA = pack_bf2(qc[0], qc[1]);
        uint32_t qhiB = pack_bf2(qc[2], qc[3]);
        float fA0 = __uint_as_float(qhiA << 16);
        float fA1 = __uint_as_float(qhiA & 0xffff0000u);
        float fB0 = __uint_as_float(qhiB << 16);
        float fB1 = __uint_as_float(qhiB & 0xffff0000u);
        uint32_t qloA = pack_bf2(qc[0] - fA0, qc[1] - fA1);
        uint32_t qloB = pack_bf2(qc[2] - fB0, qc[3] - fB1);
        uint32_t kA = pack_bf2(kc[0], kc[1]);
        uint32_t kB = pack_bf2(kc[2], kc[3]);
        *(uint32_t*)(g_Qhi + (size_t)r0 * 16 + 4 * tig) = qhiA;
        *(uint32_t*)(g_Qhi + (size_t)(r0 + 8) * 16 + 4 * tig) = qhiB;
        *(uint32_t*)(g_Qlo + (size_t)r0 * 16 + 4 * tig) = qloA;
        *(uint32_t*)(g_Qlo + (size_t)(r0 + 8) * 16 + 4 * tig) = qloB;
        *(uint32_t*)(g_Kd + (size_t)r0 * 16 + 4 * tig) = kA;
        *(uint32_t*)(g_Kd + (size_t)(r0 + 8) * 16 + 4 * tig) = kB;
    }

    // ---- V = h2 @ Wv ----
#pragma unroll
    for (int nb = 0; nb < 8; nb++) {
        float vc[4] = {0.f, 0.f, 0.f, 0.f};
        int u = 56 + 2 * nb;
        mma_bf16(vc, h0, h1, h2r, h3, fHi[u][lane], fHi[u + 1][lane]);
        mma_bf16(vc, h0, h1, h2r, h3, fLo[u][lane], fLo[u + 1][lane]);
        int colw = 8 * nb + 2 * tig;
        *(uint32_t*)&vS[lr0 * 66 + colw] = pack_bf2(vc[0], vc[1]);
        *(uint32_t*)&vS[(lr0 + 8) * 66 + colw] = pack_bf2(vc[2], vc[3]);
    }
    __syncthreads();

    // ---- transposed coalesced write ----
    {
        int c = tid & 63, half = tid >> 6;
        unsigned char* dst = g_Vt + (size_t)blockIdx.x * 8192 + (size_t)c * 128 + half * 64;
#pragma unroll
        for (int seg = 0; seg < 4; seg++) {
            uint16_t tmp[8];
#pragma unroll
            for (int u = 0; u < 8; u++)
                tmp[u] = vS[(half * 32 + seg * 8 + u) * 66 + c];
            *(uint4*)(dst + seg * 16) = *(uint4*)tmp;
        }
    }
}

// ---------------------------------------------------------------------------
// Kernel B: mma.sync bf16 flash attention. 3-stage cp.async, ldmatrix frags.
// ---------------------------------------------------------------------------
__device__ __forceinline__ void prefetch_tile(uint32_t sKb, uint32_t sVb, int tid,
                                              const unsigned char* kptr,
                                              const unsigned char* vptr) {
    if (tid < 64) cp16(sKb + tid * 16, kptr + tid * 16);
    int r0 = tid >> 3, s0 = tid & 7;
    cp16(sVb + r0 * VROW + s0 * 16, vptr + r0 * 128 + s0 * 16);
    int i1 = tid + 256;
    int r1 = i1 >> 3, s1 = i1 & 7;
    cp16(sVb + r1 * VROW + s1 * 16, vptr + r1 * 128 + s1 * 16);
    CP_COMMIT();
}

__global__ __launch_bounds__(256, 2) void attn_kernel() {
    __shared__ __align__(16) unsigned char sK[3][1024];
    __shared__ __align__(16) unsigned char sV[3][64 * VROW];

    const int tid = threadIdx.x;
    const int wid = tid >> 5, lane = tid & 31;
    const int gr = lane >> 2, tig = lane & 3;
    const int qbase = blockIdx.x * QT;
    const int kbase = blockIdx.y * KPB;
    const int tile0 = kbase >> 6;
    const int m0 = qbase + wid * 16 + gr;

    const uint32_t qa0 = *(const uint32_t*)(g_Qhi + (size_t)m0 * 16 + 4 * tig);
    const uint32_t qa1 = *(const uint32_t*)(g_Qhi + (size_t)(m0 + 8) * 16 + 4 * tig);
    const uint32_t qa2 = *(const uint32_t*)(g_Qlo + (size_t)m0 * 16 + 4 * tig);
    const uint32_t qa3 = *(const uint32_t*)(g_Qlo + (size_t)(m0 + 8) * 16 + 4 * tig);

    float o[8][4];
#pragma unroll
    for (int i = 0; i < 8; i++)
#pragma unroll
        for (int j = 0; j < 4; j++) o[i][j] = 0.f;
    float den0 = 0.f, den1 = 0.f;

    uint32_t sKb[3], sVb[3];
#pragma unroll
    for (int s = 0; s < 3; s++) { sKb[s] = smem_u32(sK[s]); sVb[s] = smem_u32(sV[s]); }

    // per-lane ldmatrix address offsets
    const uint32_t vLane = (uint32_t)((((lane >> 4) << 3) | (lane & 7)) * VROW +
                                      (((lane >> 3) & 1) << 4));
    const uint32_t kLane = (uint32_t)((lane & 15) * 16);

    prefetch_tile(sKb[0], sVb[0], tid, g_Kd + (size_t)kbase * 16, g_Vt + (size_t)tile0 * 8192);

    int st = 0;
    for (int t = 0; t < NT; t++) {
        CP_WAIT0();
        __syncthreads();
        if (t + 1 < NT) {
            int sn = (st == 2) ? 0 : st + 1;
            prefetch_tile(sKb[sn], sVb[sn], tid,
                          g_Kd + (size_t)(kbase + (t + 1) * 64) * 16,
                          g_Vt + (size_t)(tile0 + t + 1) * 8192);
        }
        const uint32_t kA = sKb[st] + kLane;
        const uint32_t vA = sVb[st] + vLane;

#pragma unroll
        for (int kc = 0; kc < 4; kc++) {
            float s0[4] = {0.f, 0.f, 0.f, 0.f};
            float s1[4] = {0.f, 0.f, 0.f, 0.f};
            uint32_t kb0, kb1;
            ldsm_x2(kb0, kb1, kA + kc * 256);
            mma_bf16(s0, qa0, qa1, qa2, qa3, kb0, kb0);
            mma_bf16(s1, qa0, qa1, qa2, qa3, kb1, kb1);

            float e00 = ex2f(s0[0]), e01 = ex2f(s0[1]), e02 = ex2f(s0[2]), e03 = ex2f(s0[3]);
            float e10 = ex2f(s1[0]), e11 = ex2f(s1[1]), e12 = ex2f(s1[2]), e13 = ex2f(s1[3]);
            den0 += (e00 + e01) + (e10 + e11);
            den1 += (e02 + e03) + (e12 + e13);
            uint32_t pa0 = pack_bf2(e00, e01);
            uint32_t pa1 = pack_bf2(e02, e03);
            uint32_t pa2 = pack_bf2(e10, e11);
            uint32_t pa3 = pack_bf2(e12, e13);

#pragma unroll
            for (int j = 0; j < 4; j++) {
                uint32_t v0, v1, v2, v3;
                ldsm_x4(v0, v1, v2, v3, vA + j * (16 * VROW) + kc * 32);
                mma_bf16(o[2 * j], pa0, pa1, pa2, pa3, v0, v1);
                mma_bf16(o[2 * j + 1], pa0, pa1, pa2, pa3, v2, v3);
            }
        }
        st = (st == 2) ? 0 : st + 1;
    }

    den0 += __shfl_xor_sync(0xffffffffu, den0, 1);
    den0 += __shfl_xor_sync(0xffffffffu, den0, 2);
    den1 += __shfl_xor_sync(0xffffffffu, den1, 1);
    den1 += __shfl_xor_sync(0xffffffffu, den1, 2);
    if (tig == 0) {
        g_den[blockIdx.y * NQ + m0] = den0;
        g_den[blockIdx.y * NQ + m0 + 8] = den1;
    }

    float* np0 = g_num + ((size_t)blockIdx.y * NQ + m0) * 64;
    float* np1 = np0 + 8 * 64;
#pragma unroll
    for (int nb = 0; nb < 8; nb++) {
        *(float2*)(np0 + 8 * nb + 2 * tig) = make_float2(o[nb][0], o[nb][1]);
        *(float2*)(np1 + 8 * nb + 2 * tig) = make_float2(o[nb][2], o[nb][3]);
    }
}

// ---------------------------------------------------------------------------
// Kernel C: combine splits + divide
// ---------------------------------------------------------------------------
__global__ void combine_kernel(float* __restrict__ out) {
    int i = blockIdx.x * blockDim.x + threadIdx.x;
    if (i >= NQ * 64) return;
    int r = i >> 6;
    float s = 0.f, d = 0.f;
#pragma unroll
    for (int p = 0; p < SPLIT; p++) {
        s += g_num[(size_t)p * NQ * 64 + i];
        d += g_den[p * NQ + r];
    }
    out[i] = s / d;
}

extern "C" void kernel_launch(void* const* d_in, const int* in_sizes, int n_in,
                              void* d_out, int out_size) {
    const float* xm = (const float*)d_in[0];
    const float* xd = (const float*)d_in[1];
    const float* W1 = (const float*)d_in[3];
    const float* W2 = (const float*)d_in[4];
    const float* Wq = (const float*)d_in[5];
    const float* Wk = (const float*)d_in[6];
    const float* Wv = (const float*)d_in[7];

    qkv_kernel<<<NQ / 64, 128>>>(xm, xd, W1, W2, Wq, Wk, Wv);
    attn_kernel<<<dim3(NQ / QT, SPLIT), 256>>>();
    combine_kernel<<<(NQ * 64 + 255) / 256, 256>>>((float*)d_out);
}

// round 10
// speedup vs baseline: 1.7235x; 1.0802x over previous
#include <cuda_runtime.h>
#include <cuda_bf16.h>
#include <cstdint>

#define NQ 12288
#define SPLIT 3
#define KPB (NQ / SPLIT)   // 4096
#define NT2 (KPB / 128)    // 32 stages of 128 keys
#define QT 128
#define VROW 144           // padded SMEM row stride for V^T (bytes)

// ---- scratch (no cudaMalloc allowed) ----
__device__ __align__(16) unsigned char g_Qhi[NQ * 16];
__device__ __align__(16) unsigned char g_Qlo[NQ * 16];
__device__ __align__(16) unsigned char g_Kd[NQ * 16];
__device__ __align__(16) unsigned char g_Vt[(NQ / 64) * 8192];
__device__ __align__(16) float g_num[SPLIT * NQ * 64];
__device__ __align__(16) float g_den[SPLIT * NQ];

// ============ helpers ============
__device__ __forceinline__ float ex2f(float x) {
    float r; asm("ex2.approx.ftz.f32 %0, %1;" : "=f"(r) : "f"(x)); return r;
}
__device__ __forceinline__ uint32_t pack_bf2(float lo, float hi) {
    uint32_t r;
    asm("cvt.rn.bf16x2.f32 %0, %1, %2;" : "=r"(r) : "f"(hi), "f"(lo));
    return r;
}
__device__ __forceinline__ void cp16(uint32_t dst, const void* src) {
    asm volatile("cp.async.ca.shared.global [%0], [%1], 16;" :: "r"(dst), "l"(src) : "memory");
}
#define CP_COMMIT() asm volatile("cp.async.commit_group;" ::: "memory")
#define CP_WAIT0()  asm volatile("cp.async.wait_group 0;" ::: "memory")

__device__ __forceinline__ uint32_t smem_u32(const void* p) {
    uint32_t a;
    asm("{ .reg .u64 t; cvta.to.shared.u64 t, %1; cvt.u32.u64 %0, t; }" : "=r"(a) : "l"(p));
    return a;
}
__device__ __forceinline__ void mma_bf16(float d[4], uint32_t a0, uint32_t a1, uint32_t a2,
                                         uint32_t a3, uint32_t b0, uint32_t b1) {
    asm volatile("mma.sync.aligned.m16n8k16.row.col.f32.bf16.bf16.f32 "
                 "{%0,%1,%2,%3}, {%4,%5,%6,%7}, {%8,%9}, {%0,%1,%2,%3};"
                 : "+f"(d[0]), "+f"(d[1]), "+f"(d[2]), "+f"(d[3])
                 : "r"(a0), "r"(a1), "r"(a2), "r"(a3), "r"(b0), "r"(b1));
}
__device__ __forceinline__ void ldsm_x4(uint32_t& r0, uint32_t& r1, uint32_t& r2, uint32_t& r3,
                                        uint32_t addr) {
    asm volatile("ldmatrix.sync.aligned.m8n8.x4.shared.b16 {%0,%1,%2,%3}, [%4];"
                 : "=r"(r0), "=r"(r1), "=r"(r2), "=r"(r3) : "r"(addr));
}
__device__ __forceinline__ void ldsm_x2(uint32_t& r0, uint32_t& r1, uint32_t addr) {
    asm volatile("ldmatrix.sync.aligned.m8n8.x2.shared.b16 {%0,%1}, [%2];"
                 : "=r"(r0), "=r"(r1) : "r"(addr));
}

// ---------------------------------------------------------------------------
// Kernel A: mma.sync QKV (R8 config: 256 threads, 128 rows, grid 96).
// ---------------------------------------------------------------------------
__global__ __launch_bounds__(256) void qkv_kernel(
    const float* __restrict__ xm, const float* __restrict__ xd,
    const float* __restrict__ W1, const float* __restrict__ W2,
    const float* __restrict__ Wq, const float* __restrict__ Wk,
    const float* __restrict__ Wv) {
    __shared__ uint32_t fHi[72][32];
    __shared__ uint32_t fLo[72][32];
    __shared__ uint16_t vS[128 * 66];

    const int tid = threadIdx.x;
    const int wid = tid >> 5, lane = tid & 31;
    const int gr = lane >> 2, tig = lane & 3;
    const float QS = (float)(1.4426950408889634 / 2.8284271247461903);

    for (int u = wid; u < 72; u += 8) {
        int k, col, stride; const float* src; float scale = 1.f;
        if (u < 48) {
            int ks = u >> 2, nb = (u >> 1) & 1, reg = u & 1;
            k = 16 * ks + 2 * tig + 8 * reg; col = gr + 8 * nb; src = W1; stride = 16;
        } else if (u < 52) {
            int v = u - 48, nb = (v >> 1) & 1, reg = v & 1;
            k = 2 * tig + 8 * reg; col = gr + 8 * nb; src = W2; stride = 16;
        } else if (u < 56) {
            int v = u - 52, nb = (v >> 1) & 1, reg = v & 1;
            k = 2 * tig + 8 * reg; col = gr; src = nb ? Wk : Wq; stride = 8;
            if (!nb) scale = QS;
        } else {
            int v = u - 56, nb = v >> 1, reg = v & 1;
            k = 2 * tig + 8 * reg; col = 8 * nb + gr; src = Wv; stride = 64;
        }
        float w0 = src[k * stride + col] * scale;
        float w1 = src[(k + 1) * stride + col] * scale;
        uint32_t hi = pack_bf2(w0, w1);
        float f0 = __uint_as_float(hi << 16);
        float f1 = __uint_as_float(hi & 0xffff0000u);
        uint32_t lo = pack_bf2(w0 - f0, w1 - f1);
        fHi[u][lane] = hi;
        fLo[u][lane] = lo;
    }
    __syncthreads();

    const int lr0 = wid * 16 + gr;
    const int r0 = blockIdx.x * 128 + lr0;

    float c0[4] = {0.f, 0.f, 0.f, 0.f}, c1[4] = {0.f, 0.f, 0.f, 0.f};
    {
        const float* pr0m = xm + (size_t)r0 * 64;
        const float* pr1m = pr0m + 8 * 64;
        const float* pr0d = xd + (size_t)r0 * 128;
        const float* pr1d = pr0d + 8 * 128;
#pragma unroll
        for (int ks = 0; ks < 12; ks++) {
            const float* p0 = (ks < 4) ? (pr0m + 16 * ks) : (pr0d + 16 * ks - 64);
            const float* p1 = (ks < 4) ? (pr1m + 16 * ks) : (pr1d + 16 * ks - 64);
            float2 x00 = *(const float2*)(p0 + 2 * tig);
            float2 x01 = *(const float2*)(p0 + 2 * tig + 8);
            float2 x10 = *(const float2*)(p1 + 2 * tig);
            float2 x11 = *(const float2*)(p1 + 2 * tig + 8);
            uint32_t a0 = pack_bf2(x00.x, x00.y);
            uint32_t a1 = pack_bf2(x10.x, x10.y);
            uint32_t a2 = pack_bf2(x01.x, x01.y);
            uint32_t a3 = pack_bf2(x11.x, x11.y);
            int u = 4 * ks;
            mma_bf16(c0, a0, a1, a2, a3, fHi[u][lane], fHi[u + 1][lane]);
            mma_bf16(c0, a0, a1, a2, a3, fLo[u][lane], fLo[u + 1][lane]);
            mma_bf16(c1, a0, a1, a2, a3, fHi[u + 2][lane], fHi[u + 3][lane]);
            mma_bf16(c1, a0, a1, a2, a3, fLo[u + 2][lane], fLo[u + 3][lane]);
        }
    }
    uint32_t a0 = pack_bf2(fmaxf(c0[0], 0.f), fmaxf(c0[1], 0.f));
    uint32_t a1 = pack_bf2(fmaxf(c0[2], 0.f), fmaxf(c0[3], 0.f));
    uint32_t a2 = pack_bf2(fmaxf(c1[0], 0.f), fmaxf(c1[1], 0.f));
    uint32_t a3 = pack_bf2(fmaxf(c1[2], 0.f), fmaxf(c1[3], 0.f));

    float d0[4] = {0.f, 0.f, 0.f, 0.f}, d1[4] = {0.f, 0.f, 0.f, 0.f};
    mma_bf16(d0, a0, a1, a2, a3, fHi[48][lane], fHi[49][lane]);
    mma_bf16(d0, a0, a1, a2, a3, fLo[48][lane], fLo[49][lane]);
    mma_bf16(d1, a0, a1, a2, a3, fHi[50][lane], fHi[51][lane]);
    mma_bf16(d1, a0, a1, a2, a3, fLo[50][lane], fLo[51][lane]);

    uint32_t h0 = pack_bf2(fmaxf(d0[0], 0.f), fmaxf(d0[1], 0.f));
    uint32_t h1 = pack_bf2(fmaxf(d0[2], 0.f), fmaxf(d0[3], 0.f));
    uint32_t h2r = pack_bf2(fmaxf(d1[0], 0.f), fmaxf(d1[1], 0.f));
    uint32_t h3 = pack_bf2(fmaxf(d1[2], 0.f), fmaxf(d1[3], 0.f));

    float qc[4] = {0.f, 0.f, 0.f, 0.f}, kc[4] = {0.f, 0.f, 0.f, 0.f};
    mma_bf16(qc, h0, h1, h2r, h3, fHi[52][lane], fHi[53][lane]);
    mma_bf16(qc, h0, h1, h2r, h3, fLo[52][lane], fLo[53][lane]);
    mma_bf16(kc, h0, h1, h2r, h3, fHi[54][lane], fHi[55][lane]);
    mma_bf16(kc, h0, h1, h2r, h3, fLo[54][lane], fLo[55][lane]);

    {
        uint32_t qhiA = pack_bf2(qc[0], qc[1]);
        uint32_t qhiB = pack_bf2(qc[2], qc[3]);
        float fA0 = __uint_as_float(qhiA << 16);
        float fA1 = __uint_as_float(qhiA & 0xffff0000u);
        float fB0 = __uint_as_float(qhiB << 16);
        float fB1 = __uint_as_float(qhiB & 0xffff0000u);
        uint32_t qloA = pack_bf2(qc[0] - fA0, qc[1] - fA1);
        uint32_t qloB = pack_bf2(qc[2] - fB0, qc[3] - fB1);
        uint32_t kA = pack_bf2(kc[0], kc[1]);
        uint32_t kB = pack_bf2(kc[2], kc[3]);
        *(uint32_t*)(g_Qhi + (size_t)r0 * 16 + 4 * tig) = qhiA;
        *(uint32_t*)(g_Qhi + (size_t)(r0 + 8) * 16 + 4 * tig) = qhiB;
        *(uint32_t*)(g_Qlo + (size_t)r0 * 16 + 4 * tig) = qloA;
        *(uint32_t*)(g_Qlo + (size_t)(r0 + 8) * 16 + 4 * tig) = qloB;
        *(uint32_t*)(g_Kd + (size_t)r0 * 16 + 4 * tig) = kA;
        *(uint32_t*)(g_Kd + (size_t)(r0 + 8) * 16 + 4 * tig) = kB;
    }

#pragma unroll
    for (int nb = 0; nb < 8; nb++) {
        float vc[4] = {0.f, 0.f, 0.f, 0.f};
        int u = 56 + 2 * nb;
        mma_bf16(vc, h0, h1, h2r, h3, fHi[u][lane], fHi[u + 1][lane]);
        mma_bf16(vc, h0, h1, h2r, h3, fLo[u][lane], fLo[u + 1][lane]);
        int colw = 8 * nb + 2 * tig;
        *(uint32_t*)&vS[lr0 * 66 + colw] = pack_bf2(vc[0], vc[1]);
        *(uint32_t*)&vS[(lr0 + 8) * 66 + colw] = pack_bf2(vc[2], vc[3]);
    }
    __syncthreads();

    if (tid < 128) {
        int tt = tid >> 6, c = tid & 63;
        unsigned char* dst = g_Vt + (size_t)(blockIdx.x * 2 + tt) * 8192 + (size_t)c * 128;
#pragma unroll
        for (int seg = 0; seg < 8; seg++) {
            uint16_t tmp[8];
#pragma unroll
            for (int u = 0; u < 8; u++)
                tmp[u] = vS[(tt * 64 + seg * 8 + u) * 66 + c];
            *(uint4*)(dst + seg * 16) = *(uint4*)tmp;
        }
    }
}

// ---------------------------------------------------------------------------
// Kernel B: mma.sync bf16 flash attention. 3-stage x 128-key stages,
// ldmatrix frags, denominator via constant-fragment ones-MMA.
// ---------------------------------------------------------------------------
__device__ __forceinline__ void prefetch_stage(uint32_t sKb, uint32_t sVb, int tid,
                                               const unsigned char* kptr,
                                               const unsigned char* vptr) {
    // K: 128 keys x 16B = 2048B
    if (tid < 128) cp16(sKb + tid * 16, kptr + tid * 16);
    // V: two 8KB tile images -> two 64-row VROW regions
#pragma unroll
    for (int i = 0; i < 4; i++) {
        int idx = tid + i * 256;          // 0..1023
        int sub = idx >> 9;               // tile image 0/1
        int rem = idx & 511;
        int r = rem >> 3, s = rem & 7;
        cp16(sVb + sub * (64 * VROW) + r * VROW + s * 16,
             vptr + sub * 8192 + r * 128 + s * 16);
    }
    CP_COMMIT();
}

__global__ __launch_bounds__(256, 2) void attn_kernel() {
    __shared__ __align__(16) unsigned char sK[3][2048];
    __shared__ __align__(16) unsigned char sV[3][2 * 64 * VROW];

    const int tid = threadIdx.x;
    const int wid = tid >> 5, lane = tid & 31;
    const int gr = lane >> 2, tig = lane & 3;
    const int qbase = blockIdx.x * QT;
    const int kbase = blockIdx.y * KPB;
    const int tile0 = kbase >> 6;
    const int m0 = qbase + wid * 16 + gr;

    const uint32_t qa0 = *(const uint32_t*)(g_Qhi + (size_t)m0 * 16 + 4 * tig);
    const uint32_t qa1 = *(const uint32_t*)(g_Qhi + (size_t)(m0 + 8) * 16 + 4 * tig);
    const uint32_t qa2 = *(const uint32_t*)(g_Qlo + (size_t)m0 * 16 + 4 * tig);
    const uint32_t qa3 = *(const uint32_t*)(g_Qlo + (size_t)(m0 + 8) * 16 + 4 * tig);

    // constant B-fragment of the all-ones column (col 0 of its n-block)
    const uint32_t bones = (lane < 4) ? 0x3F803F80u : 0u;

    float o[8][4];
#pragma unroll
    for (int i = 0; i < 8; i++)
#pragma unroll
        for (int j = 0; j < 4; j++) o[i][j] = 0.f;
    float dn[4] = {0.f, 0.f, 0.f, 0.f};

    uint32_t sKb[3], sVb[3];
#pragma unroll
    for (int s = 0; s < 3; s++) { sKb[s] = smem_u32(sK[s]); sVb[s] = smem_u32(sV[s]); }

    const uint32_t vLane = (uint32_t)((((lane >> 4) << 3) | (lane & 7)) * VROW +
                                      (((lane >> 3) & 1) << 4));
    const uint32_t kLane = (uint32_t)((lane & 15) * 16);

    prefetch_stage(sKb[0], sVb[0], tid, g_Kd + (size_t)kbase * 16,
                   g_Vt + (size_t)tile0 * 8192);

    int st = 0;
    for (int t = 0; t < NT2; t++) {
        CP_WAIT0();
        __syncthreads();
        if (t + 1 < NT2) {
            int sn = (st == 2) ? 0 : st + 1;
            prefetch_stage(sKb[sn], sVb[sn], tid,
                           g_Kd + (size_t)(kbase + (t + 1) * 128) * 16,
                           g_Vt + (size_t)(tile0 + 2 * (t + 1)) * 8192);
        }

#pragma unroll
        for (int sub = 0; sub < 2; sub++) {
            const uint32_t kA = sKb[st] + sub * 1024 + kLane;
            const uint32_t vA = sVb[st] + sub * (64 * VROW) + vLane;

#pragma unroll
            for (int kc = 0; kc < 4; kc++) {
                float s0[4] = {0.f, 0.f, 0.f, 0.f};
                float s1[4] = {0.f, 0.f, 0.f, 0.f};
                uint32_t kb0, kb1;
                ldsm_x2(kb0, kb1, kA + kc * 256);
                mma_bf16(s0, qa0, qa1, qa2, qa3, kb0, kb0);
                mma_bf16(s1, qa0, qa1, qa2, qa3, kb1, kb1);

                float e00 = ex2f(s0[0]), e01 = ex2f(s0[1]), e02 = ex2f(s0[2]), e03 = ex2f(s0[3]);
                float e10 = ex2f(s1[0]), e11 = ex2f(s1[1]), e12 = ex2f(s1[2]), e13 = ex2f(s1[3]);
                uint32_t pa0 = pack_bf2(e00, e01);
                uint32_t pa1 = pack_bf2(e02, e03);
                uint32_t pa2 = pack_bf2(e10, e11);
                uint32_t pa3 = pack_bf2(e12, e13);

                mma_bf16(dn, pa0, pa1, pa2, pa3, bones, bones);
#pragma unroll
                for (int j = 0; j < 4; j++) {
                    uint32_t v0, v1, v2, v3;
                    ldsm_x4(v0, v1, v2, v3, vA + j * (16 * VROW) + kc * 32);
                    mma_bf16(o[2 * j], pa0, pa1, pa2, pa3, v0, v1);
                    mma_bf16(o[2 * j + 1], pa0, pa1, pa2, pa3, v2, v3);
                }
            }
        }
        st = (st == 2) ? 0 : st + 1;
    }

    if (tig == 0) {
        g_den[blockIdx.y * NQ + m0] = dn[0];
        g_den[blockIdx.y * NQ + m0 + 8] = dn[2];
    }

    float* np0 = g_num + ((size_t)blockIdx.y * NQ + m0) * 64;
    float* np1 = np0 + 8 * 64;
#pragma unroll
    for (int nb = 0; nb < 8; nb++) {
        *(float2*)(np0 + 8 * nb + 2 * tig) = make_float2(o[nb][0], o[nb][1]);
        *(float2*)(np1 + 8 * nb + 2 * tig) = make_float2(o[nb][2], o[nb][3]);
    }
}

// ---------------------------------------------------------------------------
// Kernel C: combine splits + divide
// ---------------------------------------------------------------------------
__global__ void combine_kernel(float* __restrict__ out) {
    int i = blockIdx.x * blockDim.x + threadIdx.x;
    if (i >= NQ * 64) return;
    int r = i >> 6;
    float s = 0.f, d = 0.f;
#pragma unroll
    for (int p = 0; p < SPLIT; p++) {
        s += g_num[(size_t)p * NQ * 64 + i];
        d += g_den[p * NQ + r];
    }
    out[i] = s / d;
}

extern "C" void kernel_launch(void* const* d_in, const int* in_sizes, int n_in,
                              void* d_out, int out_size) {
    const float* xm = (const float*)d_in[0];
    const float* xd = (const float*)d_in[1];
    const float* W1 = (const float*)d_in[3];
    const float* W2 = (const float*)d_in[4];
    const float* Wq = (const float*)d_in[5];
    const float* Wk = (const float*)d_in[6];
    const float* Wv = (const float*)d_in[7];

    qkv_kernel<<<NQ / 128, 256>>>(xm, xd, W1, W2, Wq, Wk, Wv);
    attn_kernel<<<dim3(NQ / QT, SPLIT), 256>>>();
    combine_kernel<<<(NQ * 64 + 255) / 256, 256>>>((float*)d_out);
}

// round 11
// speedup vs baseline: 1.7703x; 1.0272x over previous
#include <cuda_runtime.h>
#include <cuda_bf16.h>
#include <cstdint>

#define NQ 12288
#define SPLIT 3
#define KPB (NQ / SPLIT)   // 4096
#define NT2 (KPB / 128)    // 32 stages of 128 keys
#define QT 128
#define VROW 144           // padded SMEM row stride for V^T (bytes)

// ---- scratch (no cudaMalloc allowed) ----
__device__ __align__(16) unsigned char g_Qhi[NQ * 16];
__device__ __align__(16) unsigned char g_Qlo[NQ * 16];
__device__ __align__(16) unsigned char g_Kd[NQ * 16];
__device__ __align__(16) unsigned char g_Vt[(NQ / 64) * 8192];
__device__ __align__(16) float g_num[SPLIT * NQ * 64];
__device__ __align__(16) float g_den[SPLIT * NQ];

// ============ helpers ============
__device__ __forceinline__ uint32_t pack_bf2(float lo, float hi) {
    uint32_t r;
    asm("cvt.rn.bf16x2.f32 %0, %1, %2;" : "=r"(r) : "f"(hi), "f"(lo));
    return r;
}
// packed bf16x2 exp2: one MUFU op per pair, result already in A-frag layout
__device__ __forceinline__ uint32_t ex2_bf2(uint32_t x) {
    uint32_t r;
    asm("ex2.approx.ftz.bf16x2 %0, %1;" : "=r"(r) : "r"(x));
    return r;
}
__device__ __forceinline__ void cp16(uint32_t dst, const void* src) {
    asm volatile("cp.async.ca.shared.global [%0], [%1], 16;" :: "r"(dst), "l"(src) : "memory");
}
#define CP_COMMIT() asm volatile("cp.async.commit_group;" ::: "memory")
#define CP_WAIT0()  asm volatile("cp.async.wait_group 0;" ::: "memory")

__device__ __forceinline__ uint32_t smem_u32(const void* p) {
    uint32_t a;
    asm("{ .reg .u64 t; cvta.to.shared.u64 t, %1; cvt.u32.u64 %0, t; }" : "=r"(a) : "l"(p));
    return a;
}
__device__ __forceinline__ void mma_bf16(float d[4], uint32_t a0, uint32_t a1, uint32_t a2,
                                         uint32_t a3, uint32_t b0, uint32_t b1) {
    asm volatile("mma.sync.aligned.m16n8k16.row.col.f32.bf16.bf16.f32 "
                 "{%0,%1,%2,%3}, {%4,%5,%6,%7}, {%8,%9}, {%0,%1,%2,%3};"
                 : "+f"(d[0]), "+f"(d[1]), "+f"(d[2]), "+f"(d[3])
                 : "r"(a0), "r"(a1), "r"(a2), "r"(a3), "r"(b0), "r"(b1));
}
__device__ __forceinline__ void ldsm_x4(uint32_t& r0, uint32_t& r1, uint32_t& r2, uint32_t& r3,
                                        uint32_t addr) {
    asm volatile("ldmatrix.sync.aligned.m8n8.x4.shared.b16 {%0,%1,%2,%3}, [%4];"
                 : "=r"(r0), "=r"(r1), "=r"(r2), "=r"(r3) : "r"(addr));
}
__device__ __forceinline__ void ldsm_x2(uint32_t& r0, uint32_t& r1, uint32_t addr) {
    asm volatile("ldmatrix.sync.aligned.m8n8.x2.shared.b16 {%0,%1}, [%2];"
                 : "=r"(r0), "=r"(r1) : "r"(addr));
}

// ---------------------------------------------------------------------------
// Kernel A: mma.sync QKV (R8 config: 256 threads, 128 rows, grid 96).
// ---------------------------------------------------------------------------
__global__ __launch_bounds__(256) void qkv_kernel(
    const float* __restrict__ xm, const float* __restrict__ xd,
    const float* __restrict__ W1, const float* __restrict__ W2,
    const float* __restrict__ Wq, const float* __restrict__ Wk,
    const float* __restrict__ Wv) {
    __shared__ uint32_t fHi[72][32];
    __shared__ uint32_t fLo[72][32];
    __shared__ uint16_t vS[128 * 66];

    const int tid = threadIdx.x;
    const int wid = tid >> 5, lane = tid & 31;
    const int gr = lane >> 2, tig = lane & 3;
    const float QS = (float)(1.4426950408889634 / 2.8284271247461903);

    for (int u = wid; u < 72; u += 8) {
        int k, col, stride; const float* src; float scale = 1.f;
        if (u < 48) {
            int ks = u >> 2, nb = (u >> 1) & 1, reg = u & 1;
            k = 16 * ks + 2 * tig + 8 * reg; col = gr + 8 * nb; src = W1; stride = 16;
        } else if (u < 52) {
            int v = u - 48, nb = (v >> 1) & 1, reg = v & 1;
            k = 2 * tig + 8 * reg; col = gr + 8 * nb; src = W2; stride = 16;
        } else if (u < 56) {
            int v = u - 52, nb = (v >> 1) & 1, reg = v & 1;
            k = 2 * tig + 8 * reg; col = gr; src = nb ? Wk : Wq; stride = 8;
            if (!nb) scale = QS;
        } else {
            int v = u - 56, nb = v >> 1, reg = v & 1;
            k = 2 * tig + 8 * reg; col = 8 * nb + gr; src = Wv; stride = 64;
        }
        float w0 = src[k * stride + col] * scale;
        float w1 = src[(k + 1) * stride + col] * scale;
        uint32_t hi = pack_bf2(w0, w1);
        float f0 = __uint_as_float(hi << 16);
        float f1 = __uint_as_float(hi & 0xffff0000u);
        uint32_t lo = pack_bf2(w0 - f0, w1 - f1);
        fHi[u][lane] = hi;
        fLo[u][lane] = lo;
    }
    __syncthreads();

    const int lr0 = wid * 16 + gr;
    const int r0 = blockIdx.x * 128 + lr0;

    float c0[4] = {0.f, 0.f, 0.f, 0.f}, c1[4] = {0.f, 0.f, 0.f, 0.f};
    {
        const float* pr0m = xm + (size_t)r0 * 64;
        const float* pr1m = pr0m + 8 * 64;
        const float* pr0d = xd + (size_t)r0 * 128;
        const float* pr1d = pr0d + 8 * 128;
#pragma unroll
        for (int ks = 0; ks < 12; ks++) {
            const float* p0 = (ks < 4) ? (pr0m + 16 * ks) : (pr0d + 16 * ks - 64);
            const float* p1 = (ks < 4) ? (pr1m + 16 * ks) : (pr1d + 16 * ks - 64);
            float2 x00 = *(const float2*)(p0 + 2 * tig);
            float2 x01 = *(const float2*)(p0 + 2 * tig + 8);
            float2 x10 = *(const float2*)(p1 + 2 * tig);
            float2 x11 = *(const float2*)(p1 + 2 * tig + 8);
            uint32_t a0 = pack_bf2(x00.x, x00.y);
            uint32_t a1 = pack_bf2(x10.x, x10.y);
            uint32_t a2 = pack_bf2(x01.x, x01.y);
            uint32_t a3 = pack_bf2(x11.x, x11.y);
            int u = 4 * ks;
            mma_bf16(c0, a0, a1, a2, a3, fHi[u][lane], fHi[u + 1][lane]);
            mma_bf16(c0, a0, a1, a2, a3, fLo[u][lane], fLo[u + 1][lane]);
            mma_bf16(c1, a0, a1, a2, a3, fHi[u + 2][lane], fHi[u + 3][lane]);
            mma_bf16(c1, a0, a1, a2, a3, fLo[u + 2][lane], fLo[u + 3][lane]);
        }
    }
    uint32_t a0 = pack_bf2(fmaxf(c0[0], 0.f), fmaxf(c0[1], 0.f));
    uint32_t a1 = pack_bf2(fmaxf(c0[2], 0.f), fmaxf(c0[3], 0.f));
    uint32_t a2 = pack_bf2(fmaxf(c1[0], 0.f), fmaxf(c1[1], 0.f));
    uint32_t a3 = pack_bf2(fmaxf(c1[2], 0.f), fmaxf(c1[3], 0.f));

    float d0[4] = {0.f, 0.f, 0.f, 0.f}, d1[4] = {0.f, 0.f, 0.f, 0.f};
    mma_bf16(d0, a0, a1, a2, a3, fHi[48][lane], fHi[49][lane]);
    mma_bf16(d0, a0, a1, a2, a3, fLo[48][lane], fLo[49][lane]);
    mma_bf16(d1, a0, a1, a2, a3, fHi[50][lane], fHi[51][lane]);
    mma_bf16(d1, a0, a1, a2, a3, fLo[50][lane], fLo[51][lane]);

    uint32_t h0 = pack_bf2(fmaxf(d0[0], 0.f), fmaxf(d0[1], 0.f));
    uint32_t h1 = pack_bf2(fmaxf(d0[2], 0.f), fmaxf(d0[3], 0.f));
    uint32_t h2r = pack_bf2(fmaxf(d1[0], 0.f), fmaxf(d1[1], 0.f));
    uint32_t h3 = pack_bf2(fmaxf(d1[2], 0.f), fmaxf(d1[3], 0.f));

    float qc[4] = {0.f, 0.f, 0.f, 0.f}, kc[4] = {0.f, 0.f, 0.f, 0.f};
    mma_bf16(qc, h0, h1, h2r, h3, fHi[52][lane], fHi[53][lane]);
    mma_bf16(qc, h0, h1, h2r, h3, fLo[52][lane], fLo[53][lane]);
    mma_bf16(kc, h0, h1, h2r, h3, fHi[54][lane], fHi[55][lane]);
    mma_bf16(kc, h0, h1, h2r, h3, fLo[54][lane], fLo[55][lane]);

    {
        uint32_t qhiA = pack_bf2(qc[0], qc[1]);
        uint32_t qhiB = pack_bf2(qc[2], qc[3]);
        float fA0 = __uint_as_float(qhiA << 16);
        float fA1 = __uint_as_float(qhiA & 0xffff0000u);
        float fB0 = __uint_as_float(qhiB << 16);
        float fB1 = __uint_as_float(qhiB & 0xffff0000u);
        uint32_t qloA = pack_bf2(qc[0] - fA0, qc[1] - fA1);
        uint32_t qloB = pack_bf2(qc[2] - fB0, qc[3] - fB1);
        uint32_t kA = pack_bf2(kc[0], kc[1]);
        uint32_t kB = pack_bf2(kc[2], kc[3]);
        *(uint32_t*)(g_Qhi + (size_t)r0 * 16 + 4 * tig) = qhiA;
        *(uint32_t*)(g_Qhi + (size_t)(r0 + 8) * 16 + 4 * tig) = qhiB;
        *(uint32_t*)(g_Qlo + (size_t)r0 * 16 + 4 * tig) = qloA;
        *(uint32_t*)(g_Qlo + (size_t)(r0 + 8) * 16 + 4 * tig) = qloB;
        *(uint32_t*)(g_Kd + (size_t)r0 * 16 + 4 * tig) = kA;
        *(uint32_t*)(g_Kd + (size_t)(r0 + 8) * 16 + 4 * tig) = kB;
    }

#pragma unroll
    for (int nb = 0; nb < 8; nb++) {
        float vc[4] = {0.f, 0.f, 0.f, 0.f};
        int u = 56 + 2 * nb;
        mma_bf16(vc, h0, h1, h2r, h3, fHi[u][lane], fHi[u + 1][lane]);
        mma_bf16(vc, h0, h1, h2r, h3, fLo[u][lane], fLo[u + 1][lane]);
        int colw = 8 * nb + 2 * tig;
        *(uint32_t*)&vS[lr0 * 66 + colw] = pack_bf2(vc[0], vc[1]);
        *(uint32_t*)&vS[(lr0 + 8) * 66 + colw] = pack_bf2(vc[2], vc[3]);
    }
    __syncthreads();

    if (tid < 128) {
        int tt = tid >> 6, c = tid & 63;
        unsigned char* dst = g_Vt + (size_t)(blockIdx.x * 2 + tt) * 8192 + (size_t)c * 128;
#pragma unroll
        for (int seg = 0; seg < 8; seg++) {
            uint16_t tmp[8];
#pragma unroll
            for (int u = 0; u < 8; u++)
                tmp[u] = vS[(tt * 64 + seg * 8 + u) * 66 + c];
            *(uint4*)(dst + seg * 16) = *(uint4*)tmp;
        }
    }
}

// ---------------------------------------------------------------------------
// Kernel B: mma.sync bf16 flash attention. 3-stage x 128-key stages,
// ldmatrix frags, packed bf16x2 exp, ones-MMA denominator.
// ---------------------------------------------------------------------------
__device__ __forceinline__ void prefetch_stage(uint32_t sKb, uint32_t sVb, int tid,
                                               const unsigned char* kptr,
                                               const unsigned char* vptr) {
    if (tid < 128) cp16(sKb + tid * 16, kptr + tid * 16);
#pragma unroll
    for (int i = 0; i < 4; i++) {
        int idx = tid + i * 256;
        int sub = idx >> 9;
        int rem = idx & 511;
        int r = rem >> 3, s = rem & 7;
        cp16(sVb + sub * (64 * VROW) + r * VROW + s * 16,
             vptr + sub * 8192 + r * 128 + s * 16);
    }
    CP_COMMIT();
}

__global__ __launch_bounds__(256, 2) void attn_kernel() {
    __shared__ __align__(16) unsigned char sK[3][2048];
    __shared__ __align__(16) unsigned char sV[3][2 * 64 * VROW];

    const int tid = threadIdx.x;
    const int wid = tid >> 5, lane = tid & 31;
    const int gr = lane >> 2, tig = lane & 3;
    const int qbase = blockIdx.x * QT;
    const int kbase = blockIdx.y * KPB;
    const int tile0 = kbase >> 6;
    const int m0 = qbase + wid * 16 + gr;

    const uint32_t qa0 = *(const uint32_t*)(g_Qhi + (size_t)m0 * 16 + 4 * tig);
    const uint32_t qa1 = *(const uint32_t*)(g_Qhi + (size_t)(m0 + 8) * 16 + 4 * tig);
    const uint32_t qa2 = *(const uint32_t*)(g_Qlo + (size_t)m0 * 16 + 4 * tig);
    const uint32_t qa3 = *(const uint32_t*)(g_Qlo + (size_t)(m0 + 8) * 16 + 4 * tig);

    const uint32_t bones = (lane < 4) ? 0x3F803F80u : 0u;

    float o[8][4];
#pragma unroll
    for (int i = 0; i < 8; i++)
#pragma unroll
        for (int j = 0; j < 4; j++) o[i][j] = 0.f;
    float dn[4] = {0.f, 0.f, 0.f, 0.f};

    uint32_t sKb[3], sVb[3];
#pragma unroll
    for (int s = 0; s < 3; s++) { sKb[s] = smem_u32(sK[s]); sVb[s] = smem_u32(sV[s]); }

    const uint32_t vLane = (uint32_t)((((lane >> 4) << 3) | (lane & 7)) * VROW +
                                      (((lane >> 3) & 1) << 4));
    const uint32_t kLane = (uint32_t)((lane & 15) * 16);

    prefetch_stage(sKb[0], sVb[0], tid, g_Kd + (size_t)kbase * 16,
                   g_Vt + (size_t)tile0 * 8192);

    int st = 0;
    for (int t = 0; t < NT2; t++) {
        CP_WAIT0();
        __syncthreads();
        if (t + 1 < NT2) {
            int sn = (st == 2) ? 0 : st + 1;
            prefetch_stage(sKb[sn], sVb[sn], tid,
                           g_Kd + (size_t)(kbase + (t + 1) * 128) * 16,
                           g_Vt + (size_t)(tile0 + 2 * (t + 1)) * 8192);
        }

#pragma unroll
        for (int sub = 0; sub < 2; sub++) {
            const uint32_t kA = sKb[st] + sub * 1024 + kLane;
            const uint32_t vA = sVb[st] + sub * (64 * VROW) + vLane;

#pragma unroll
            for (int kc = 0; kc < 4; kc++) {
                float s0[4] = {0.f, 0.f, 0.f, 0.f};
                float s1[4] = {0.f, 0.f, 0.f, 0.f};
                uint32_t kb0, kb1;
                ldsm_x2(kb0, kb1, kA + kc * 256);
                mma_bf16(s0, qa0, qa1, qa2, qa3, kb0, kb0);
                mma_bf16(s1, qa0, qa1, qa2, qa3, kb1, kb1);

                // packed bf16x2 exp: scores -> bf16x2 -> ex2 (A-frag layout)
                uint32_t pa0 = ex2_bf2(pack_bf2(s0[0], s0[1]));
                uint32_t pa1 = ex2_bf2(pack_bf2(s0[2], s0[3]));
                uint32_t pa2 = ex2_bf2(pack_bf2(s1[0], s1[1]));
                uint32_t pa3 = ex2_bf2(pack_bf2(s1[2], s1[3]));

                mma_bf16(dn, pa0, pa1, pa2, pa3, bones, bones);
#pragma unroll
                for (int j = 0; j < 4; j++) {
                    uint32_t v0, v1, v2, v3;
                    ldsm_x4(v0, v1, v2, v3, vA + j * (16 * VROW) + kc * 32);
                    mma_bf16(o[2 * j], pa0, pa1, pa2, pa3, v0, v1);
                    mma_bf16(o[2 * j + 1], pa0, pa1, pa2, pa3, v2, v3);
                }
            }
        }
        st = (st == 2) ? 0 : st + 1;
    }

    if (tig == 0) {
        g_den[blockIdx.y * NQ + m0] = dn[0];
        g_den[blockIdx.y * NQ + m0 + 8] = dn[2];
    }

    float* np0 = g_num + ((size_t)blockIdx.y * NQ + m0) * 64;
    float* np1 = np0 + 8 * 64;
#pragma unroll
    for (int nb = 0; nb < 8; nb++) {
        *(float2*)(np0 + 8 * nb + 2 * tig) = make_float2(o[nb][0], o[nb][1]);
        *(float2*)(np1 + 8 * nb + 2 * tig) = make_float2(o[nb][2], o[nb][3]);
    }
}

// ---------------------------------------------------------------------------
// Kernel C: combine splits + divide
// ---------------------------------------------------------------------------
__global__ void combine_kernel(float* __restrict__ out) {
    int i = blockIdx.x * blockDim.x + threadIdx.x;
    if (i >= NQ * 64) return;
    int r = i >> 6;
    float s = 0.f, d = 0.f;
#pragma unroll
    for (int p = 0; p < SPLIT; p++) {
        s += g_num[(size_t)p * NQ * 64 + i];
        d += g_den[p * NQ + r];
    }
    out[i] = s / d;
}

extern "C" void kernel_launch(void* const* d_in, const int* in_sizes, int n_in,
                              void* d_out, int out_size) {
    const float* xm = (const float*)d_in[0];
    const float* xd = (const float*)d_in[1];
    const float* W1 = (const float*)d_in[3];
    const float* W2 = (const float*)d_in[4];
    const float* Wq = (const float*)d_in[5];
    const float* Wk = (const float*)d_in[6];
    const float* Wv = (const float*)d_in[7];

    qkv_kernel<<<NQ / 128, 256>>>(xm, xd, W1, W2, Wq, Wk, Wv);
    attn_kernel<<<dim3(NQ / QT, SPLIT), 256>>>();
    combine_kernel<<<(NQ * 64 + 255) / 256, 256>>>((float*)d_out);
}